// round 9
// baseline (speedup 1.0000x reference)
#include <cuda_runtime.h>
#include <cuda_bf16.h>
#include <cstdint>

#define T_LEN 256
#define B_SZ  64
#define H_SZ  1024
#define K_IN  2048
#define G3H   3072
#define MROWS (T_LEN * B_SZ)   // 16384

// ---------------- scratch (device globals; no allocation allowed) ----------
static __device__ float g_gx[2][MROWS * G3H];        // per-dir input gates, fp32
static __device__ float g_seq[MROWS * 2 * H_SZ];     // layer output sequence [T,B,2H]
static __device__ float g_h[2][2][B_SZ * H_SZ];      // [parity][dir][B*H] hidden ping-pong

// ---------------- helpers --------------------------------------------------
__device__ __forceinline__ void mma_bf16(float (&c)[4], const uint32_t (&a)[4],
                                         const uint32_t (&b)[2]) {
    asm volatile(
        "mma.sync.aligned.m16n8k16.row.col.f32.bf16.bf16.f32 "
        "{%0,%1,%2,%3}, {%4,%5,%6,%7}, {%8,%9}, {%0,%1,%2,%3};\n"
        : "+f"(c[0]), "+f"(c[1]), "+f"(c[2]), "+f"(c[3])
        : "r"(a[0]), "r"(a[1]), "r"(a[2]), "r"(a[3]), "r"(b[0]), "r"(b[1]));
}

// fp32x4 -> (hi,lo) bf16 split, stored as 2x uint32 each (4 consecutive elems)
__device__ __forceinline__ void split4(const float4 v, __nv_bfloat16* hi, __nv_bfloat16* lo) {
    float f[4] = {v.x, v.y, v.z, v.w};
    unsigned short hb[4], lb[4];
#pragma unroll
    for (int i = 0; i < 4; i++) {
        __nv_bfloat16 h = __float2bfloat16_rn(f[i]);
        float r = f[i] - __bfloat162float(h);          // exact (Sterbenz)
        __nv_bfloat16 l = __float2bfloat16_rn(r);
        hb[i] = __bfloat16_as_ushort(h);
        lb[i] = __bfloat16_as_ushort(l);
    }
    *reinterpret_cast<uint32_t*>(hi)     = (uint32_t)hb[0] | ((uint32_t)hb[1] << 16);
    *reinterpret_cast<uint32_t*>(hi + 2) = (uint32_t)hb[2] | ((uint32_t)hb[3] << 16);
    *reinterpret_cast<uint32_t*>(lo)     = (uint32_t)lb[0] | ((uint32_t)lb[1] << 16);
    *reinterpret_cast<uint32_t*>(lo + 2) = (uint32_t)lb[2] | ((uint32_t)lb[3] << 16);
}

__device__ __forceinline__ float sigmoidf_(float x) {
    return 1.0f / (1.0f + __expf(-x));
}

// ---------------- input-projection GEMM ------------------------------------
// C[16384,3072] = A[16384,2048] @ W[3072,2048]^T + bias, split-bf16 3-term.
// Tiles: BM=128 BN=128 BK=32, 256 threads (8 warps, 4x2), warp tile 32x64.
__global__ __launch_bounds__(256) void gru_gemm_in(
    const float* __restrict__ Aopt,   // null -> use g_seq
    const float* __restrict__ W,
    const float* __restrict__ bias,
    int dirIdx)
{
    const float* A = Aopt ? Aopt : g_seq;
    float* C = g_gx[dirIdx];

    __shared__ __nv_bfloat16 Ah[128][40];
    __shared__ __nv_bfloat16 Al[128][40];
    __shared__ __nv_bfloat16 Bh[128][40];
    __shared__ __nv_bfloat16 Bl[128][40];

    const int tid  = threadIdx.x;
    const int lane = tid & 31;
    const int warp = tid >> 5;
    const int wm   = warp >> 1;   // 0..3
    const int wn   = warp & 1;    // 0..1
    const int m0   = blockIdx.y * 128;
    const int n0   = blockIdx.x * 128;

    float acc[2][8][4];
#pragma unroll
    for (int i = 0; i < 2; i++)
#pragma unroll
        for (int j = 0; j < 8; j++)
#pragma unroll
            for (int k = 0; k < 4; k++) acc[i][j][k] = 0.f;

    const int c4 = (tid & 7) * 4;   // k offset of this thread's float4
    const int r0 = tid >> 3;        // base row (stride 32 per i)

    float4 ra[4], rb[4];
#pragma unroll
    for (int i = 0; i < 4; i++) {
        ra[i] = *reinterpret_cast<const float4*>(&A[(m0 + r0 + i * 32) * K_IN + c4]);
        rb[i] = *reinterpret_cast<const float4*>(&W[(n0 + r0 + i * 32) * K_IN + c4]);
    }

    for (int kt = 0; kt < K_IN; kt += 32) {
#pragma unroll
        for (int i = 0; i < 4; i++) {
            split4(ra[i], &Ah[r0 + i * 32][c4], &Al[r0 + i * 32][c4]);
            split4(rb[i], &Bh[r0 + i * 32][c4], &Bl[r0 + i * 32][c4]);
        }
        __syncthreads();
        if (kt + 32 < K_IN) {
#pragma unroll
            for (int i = 0; i < 4; i++) {
                ra[i] = *reinterpret_cast<const float4*>(&A[(m0 + r0 + i * 32) * K_IN + kt + 32 + c4]);
                rb[i] = *reinterpret_cast<const float4*>(&W[(n0 + r0 + i * 32) * K_IN + kt + 32 + c4]);
            }
        }
#pragma unroll
        for (int k16 = 0; k16 < 2; k16++) {
            const int kk   = k16 * 16 + (lane & 3) * 2;
            const int arow = wm * 32 + (lane >> 2);
            uint32_t ahf[2][4], alf[2][4];
#pragma unroll
            for (int mt = 0; mt < 2; mt++) {
                const int rr = arow + mt * 16;
                ahf[mt][0] = *reinterpret_cast<const uint32_t*>(&Ah[rr][kk]);
                ahf[mt][1] = *reinterpret_cast<const uint32_t*>(&Ah[rr + 8][kk]);
                ahf[mt][2] = *reinterpret_cast<const uint32_t*>(&Ah[rr][kk + 8]);
                ahf[mt][3] = *reinterpret_cast<const uint32_t*>(&Ah[rr + 8][kk + 8]);
                alf[mt][0] = *reinterpret_cast<const uint32_t*>(&Al[rr][kk]);
                alf[mt][1] = *reinterpret_cast<const uint32_t*>(&Al[rr + 8][kk]);
                alf[mt][2] = *reinterpret_cast<const uint32_t*>(&Al[rr][kk + 8]);
                alf[mt][3] = *reinterpret_cast<const uint32_t*>(&Al[rr + 8][kk + 8]);
            }
            uint32_t bhf[8][2], blf[8][2];
            const int brow = wn * 64 + (lane >> 2);
#pragma unroll
            for (int nt = 0; nt < 8; nt++) {
                const int rr = brow + nt * 8;
                bhf[nt][0] = *reinterpret_cast<const uint32_t*>(&Bh[rr][kk]);
                bhf[nt][1] = *reinterpret_cast<const uint32_t*>(&Bh[rr][kk + 8]);
                blf[nt][0] = *reinterpret_cast<const uint32_t*>(&Bl[rr][kk]);
                blf[nt][1] = *reinterpret_cast<const uint32_t*>(&Bl[rr][kk + 8]);
            }
#pragma unroll
            for (int mt = 0; mt < 2; mt++)
#pragma unroll
                for (int nt = 0; nt < 8; nt++) {
                    mma_bf16(acc[mt][nt], ahf[mt], bhf[nt]);
                    mma_bf16(acc[mt][nt], ahf[mt], blf[nt]);
                    mma_bf16(acc[mt][nt], alf[mt], bhf[nt]);
                }
        }
        __syncthreads();
    }

    // epilogue: + bias, write fp32 gx
#pragma unroll
    for (int mt = 0; mt < 2; mt++)
#pragma unroll
        for (int nt = 0; nt < 8; nt++) {
            const int row = m0 + wm * 32 + mt * 16 + (lane >> 2);
            const int col = n0 + wn * 64 + nt * 8 + (lane & 3) * 2;
            const float b0 = bias[col], b1 = bias[col + 1];
            C[row * G3H + col]           = acc[mt][nt][0] + b0;
            C[row * G3H + col + 1]       = acc[mt][nt][1] + b1;
            C[(row + 8) * G3H + col]     = acc[mt][nt][2] + b0;
            C[(row + 8) * G3H + col + 1] = acc[mt][nt][3] + b1;
        }
}

// ---------------- recurrent step kernel ------------------------------------
// grid (64, 2): blockIdx.x selects 16 hidden columns (same cols of all 3 gates),
// blockIdx.y = direction. Block: 128 threads (4 warps, one m16 row-tile each).
// Computes gh[64 x 48] = h @ Whh^T slab, then fused GRU gate math + writes.
__global__ __launch_bounds__(128) void gru_step(
    const float* __restrict__ whh_l,   // layer base: [2][3072][1024]
    const float* __restrict__ bhh_l,   // layer base: [2][3072]
    int s, int layer, int lastFlag,
    float* __restrict__ dout)
{
    const int dir = blockIdx.y;
    const int nc0 = blockIdx.x * 16;
    const float* whh = whh_l + dir * G3H * H_SZ;
    const float* bhh = bhh_l + dir * G3H;
    const float* gx  = g_gx[dir];
    const int par = s & 1;
    const float* hr = g_h[par][dir];
    float* hw = g_h[par ^ 1][dir];
    const int t = dir ? (T_LEN - 1 - s) : s;

    __shared__ __nv_bfloat16 Ah[64][72];
    __shared__ __nv_bfloat16 Al[64][72];
    __shared__ __nv_bfloat16 Bh[48][72];
    __shared__ __nv_bfloat16 Bl[48][72];

    const int tid  = threadIdx.x;
    const int lane = tid & 31;
    const int warp = tid >> 5;

    float acc[6][4];
#pragma unroll
    for (int i = 0; i < 6; i++)
#pragma unroll
        for (int j = 0; j < 4; j++) acc[i][j] = 0.f;

    const int c4 = (tid & 15) * 4;
    const int r0 = tid >> 4;     // 0..7, stride 8 per i

    float4 ra[8], rb[6];
#pragma unroll
    for (int i = 0; i < 8; i++)
        ra[i] = *reinterpret_cast<const float4*>(&hr[(r0 + i * 8) * H_SZ + c4]);
#pragma unroll
    for (int i = 0; i < 6; i++) {
        const int row = r0 + i * 8;
        const int grow = (row >> 4) * H_SZ + nc0 + (row & 15);
        rb[i] = *reinterpret_cast<const float4*>(&whh[grow * H_SZ + c4]);
    }

    for (int kt = 0; kt < H_SZ; kt += 64) {
#pragma unroll
        for (int i = 0; i < 8; i++)
            split4(ra[i], &Ah[r0 + i * 8][c4], &Al[r0 + i * 8][c4]);
#pragma unroll
        for (int i = 0; i < 6; i++)
            split4(rb[i], &Bh[r0 + i * 8][c4], &Bl[r0 + i * 8][c4]);
        __syncthreads();
        if (kt + 64 < H_SZ) {
#pragma unroll
            for (int i = 0; i < 8; i++)
                ra[i] = *reinterpret_cast<const float4*>(&hr[(r0 + i * 8) * H_SZ + kt + 64 + c4]);
#pragma unroll
            for (int i = 0; i < 6; i++) {
                const int row = r0 + i * 8;
                const int grow = (row >> 4) * H_SZ + nc0 + (row & 15);
                rb[i] = *reinterpret_cast<const float4*>(&whh[grow * H_SZ + kt + 64 + c4]);
            }
        }
#pragma unroll
        for (int k16 = 0; k16 < 4; k16++) {
            const int kk   = k16 * 16 + (lane & 3) * 2;
            const int arow = warp * 16 + (lane >> 2);
            uint32_t ahf[4], alf[4];
            ahf[0] = *reinterpret_cast<const uint32_t*>(&Ah[arow][kk]);
            ahf[1] = *reinterpret_cast<const uint32_t*>(&Ah[arow + 8][kk]);
            ahf[2] = *reinterpret_cast<const uint32_t*>(&Ah[arow][kk + 8]);
            ahf[3] = *reinterpret_cast<const uint32_t*>(&Ah[arow + 8][kk + 8]);
            alf[0] = *reinterpret_cast<const uint32_t*>(&Al[arow][kk]);
            alf[1] = *reinterpret_cast<const uint32_t*>(&Al[arow + 8][kk]);
            alf[2] = *reinterpret_cast<const uint32_t*>(&Al[arow][kk + 8]);
            alf[3] = *reinterpret_cast<const uint32_t*>(&Al[arow + 8][kk + 8]);
            uint32_t bhf[6][2], blf[6][2];
            const int brow = lane >> 2;
#pragma unroll
            for (int nt = 0; nt < 6; nt++) {
                const int rr = brow + nt * 8;
                bhf[nt][0] = *reinterpret_cast<const uint32_t*>(&Bh[rr][kk]);
                bhf[nt][1] = *reinterpret_cast<const uint32_t*>(&Bh[rr][kk + 8]);
                blf[nt][0] = *reinterpret_cast<const uint32_t*>(&Bl[rr][kk]);
                blf[nt][1] = *reinterpret_cast<const uint32_t*>(&Bl[rr][kk + 8]);
            }
#pragma unroll
            for (int nt = 0; nt < 6; nt++) {
                mma_bf16(acc[nt], ahf, bhf[nt]);
                mma_bf16(acc[nt], ahf, blf[nt]);
                mma_bf16(acc[nt], alf, bhf[nt]);
            }
        }
        __syncthreads();
    }

    // fused GRU gate epilogue.
    // acc tile layout: tiles 0,1 -> gate r cols [0,16); 2,3 -> z; 4,5 -> n.
    const int rbase = warp * 16 + (lane >> 2);
#pragma unroll
    for (int rs = 0; rs < 2; rs++) {
        const int b = rbase + rs * 8;
#pragma unroll
        for (int tp = 0; tp < 2; tp++) {
#pragma unroll
            for (int j = 0; j < 2; j++) {
                const int reg = rs * 2 + j;
                const int c = nc0 + tp * 8 + (lane & 3) * 2 + j;
                float ghr = acc[tp][reg]     + bhh[c];
                float ghz = acc[tp + 2][reg] + bhh[H_SZ + c];
                float ghn = acc[tp + 4][reg] + bhh[2 * H_SZ + c];
                const float* gxrow = &gx[(t * B_SZ + b) * G3H];
                float rg = sigmoidf_(gxrow[c] + ghr);
                float zg = sigmoidf_(gxrow[H_SZ + c] + ghz);
                float ng = tanhf(gxrow[2 * H_SZ + c] + rg * ghn);
                float hp = hr[b * H_SZ + c];
                float hn = ng + zg * (hp - ng);
                hw[b * H_SZ + c] = hn;
                g_seq[(t * B_SZ + b) * (2 * H_SZ) + dir * H_SZ + c] = hn;
                if (lastFlag)
                    dout[(layer * 2 + dir) * B_SZ * H_SZ + b * H_SZ + c] = hn;
            }
        }
    }
}

// ---------------- init hidden state ----------------------------------------
__global__ void gru_init_h(const float* __restrict__ h0l) {
    const int i = blockIdx.x * blockDim.x + threadIdx.x;
    if (i < 2 * B_SZ * H_SZ) g_h[0][0][i] = h0l[i];   // covers both dirs (contiguous)
}

// ---------------- launch ----------------------------------------------------
extern "C" void kernel_launch(void* const* d_in, const int* in_sizes, int n_in,
                              void* d_out, int out_size) {
    const float* x   = (const float*)d_in[0];   // [T,B,2048]
    const float* h0  = (const float*)d_in[1];   // [6,B,H]
    const float* wih = (const float*)d_in[2];   // [3,2,3072,2048]
    const float* whh = (const float*)d_in[3];   // [3,2,3072,1024]
    const float* bih = (const float*)d_in[4];   // [3,2,3072]
    const float* bhh = (const float*)d_in[5];   // [3,2,3072]
    float* out = (float*)d_out;                 // [6,B,H]

    const dim3 ggrid(G3H / 128, MROWS / 128);   // (24, 128)
    const dim3 sgrid(H_SZ / 16, 2);             // (64, 2)

    for (int l = 0; l < 3; l++) {
        const float* Ain = (l == 0) ? x : nullptr;   // null => g_seq
        for (int d = 0; d < 2; d++) {
            gru_gemm_in<<<ggrid, 256>>>(Ain,
                                        wih + (l * 2 + d) * G3H * K_IN,
                                        bih + (l * 2 + d) * G3H, d);
        }
        gru_init_h<<<(2 * B_SZ * H_SZ + 255) / 256, 256>>>(h0 + l * 2 * B_SZ * H_SZ);
        const float* whh_l = whh + l * 2 * G3H * H_SZ;
        const float* bhh_l = bhh + l * 2 * G3H;
        for (int s = 0; s < T_LEN; s++) {
            gru_step<<<sgrid, 128>>>(whh_l, bhh_l, s, l, (s == T_LEN - 1) ? 1 : 0, out);
        }
    }
}

// round 10
// speedup vs baseline: 1.1001x; 1.1001x over previous
#include <cuda_runtime.h>
#include <cuda_bf16.h>
#include <cstdint>

#define T_LEN 256
#define B_SZ  64
#define H_SZ  1024
#define K_IN  2048
#define G3H   3072
#define MROWS (T_LEN * B_SZ)   // 16384

#define NBLK   128              // persistent blocks (64 col-tiles x 2 dirs)
#define CHUNK  32               // K chunk for h staging
#define NCHUNK (H_SZ / CHUNK)   // 32
#define BPAD   1032             // Whh smem row stride (bf16 elems)
#define APAD   40               // h-chunk smem row stride (bf16 elems)
#define SMEM_BYTES ((2 * 48 * BPAD + 2 * 2 * 64 * APAD) * 2)  // 218624

// ---------------- scratch (device globals; no allocation allowed) ----------
static __device__ float g_gx[2][MROWS * G3H];        // per-dir input gates, fp32
static __device__ float g_seq[MROWS * 2 * H_SZ];     // layer output sequence [T,B,2H]
static __device__ __align__(16) __nv_bfloat16 g_hs[2][2][2][B_SZ * H_SZ]; // [dir][par][hi/lo]
static __device__ float g_hf[2][2][B_SZ * H_SZ];     // exact fp32 h [par][dir]

// ---------------- grid barrier ---------------------------------------------
static __device__ unsigned g_cnt = 0;
static __device__ volatile unsigned g_gen = 0;

__device__ __forceinline__ void grid_barrier() {
    __syncthreads();
    if (threadIdx.x == 0) {
        __threadfence();
        unsigned gen = g_gen;
        if (atomicAdd(&g_cnt, 1) == NBLK - 1) {
            g_cnt = 0;
            __threadfence();
            g_gen = gen + 1;
        } else {
            while (g_gen == gen) { __nanosleep(64); }
        }
        __threadfence();
    }
    __syncthreads();
}

// ---------------- helpers --------------------------------------------------
__device__ __forceinline__ void mma_bf16(float (&c)[4], const uint32_t (&a)[4],
                                         const uint32_t (&b)[2]) {
    asm volatile(
        "mma.sync.aligned.m16n8k16.row.col.f32.bf16.bf16.f32 "
        "{%0,%1,%2,%3}, {%4,%5,%6,%7}, {%8,%9}, {%0,%1,%2,%3};\n"
        : "+f"(c[0]), "+f"(c[1]), "+f"(c[2]), "+f"(c[3])
        : "r"(a[0]), "r"(a[1]), "r"(a[2]), "r"(a[3]), "r"(b[0]), "r"(b[1]));
}
__device__ __forceinline__ void mma_bf16(float (&c)[4], const uint32_t (&a)[4],
                                         uint32_t b0, uint32_t b1) {
    asm volatile(
        "mma.sync.aligned.m16n8k16.row.col.f32.bf16.bf16.f32 "
        "{%0,%1,%2,%3}, {%4,%5,%6,%7}, {%8,%9}, {%0,%1,%2,%3};\n"
        : "+f"(c[0]), "+f"(c[1]), "+f"(c[2]), "+f"(c[3])
        : "r"(a[0]), "r"(a[1]), "r"(a[2]), "r"(a[3]), "r"(b0), "r"(b1));
}

__device__ __forceinline__ void ldsm_x4(uint32_t* r, const void* p) {
    uint32_t a = (uint32_t)__cvta_generic_to_shared(p);
    asm volatile("ldmatrix.sync.aligned.m8n8.x4.shared.b16 {%0,%1,%2,%3}, [%4];\n"
                 : "=r"(r[0]), "=r"(r[1]), "=r"(r[2]), "=r"(r[3]) : "r"(a));
}

__device__ __forceinline__ void cp16(void* s, const void* g) {
    uint32_t sa = (uint32_t)__cvta_generic_to_shared(s);
    asm volatile("cp.async.cg.shared.global [%0], [%1], 16;\n" :: "r"(sa), "l"(g));
}

// fp32x4 -> (hi,lo) bf16 split, stored as 2x uint32 each (4 consecutive elems)
__device__ __forceinline__ void split4(const float4 v, __nv_bfloat16* hi, __nv_bfloat16* lo) {
    float f[4] = {v.x, v.y, v.z, v.w};
    unsigned short hb[4], lb[4];
#pragma unroll
    for (int i = 0; i < 4; i++) {
        __nv_bfloat16 h = __float2bfloat16_rn(f[i]);
        float r = f[i] - __bfloat162float(h);
        __nv_bfloat16 l = __float2bfloat16_rn(r);
        hb[i] = __bfloat16_as_ushort(h);
        lb[i] = __bfloat16_as_ushort(l);
    }
    *reinterpret_cast<uint32_t*>(hi)     = (uint32_t)hb[0] | ((uint32_t)hb[1] << 16);
    *reinterpret_cast<uint32_t*>(hi + 2) = (uint32_t)hb[2] | ((uint32_t)hb[3] << 16);
    *reinterpret_cast<uint32_t*>(lo)     = (uint32_t)lb[0] | ((uint32_t)lb[1] << 16);
    *reinterpret_cast<uint32_t*>(lo + 2) = (uint32_t)lb[2] | ((uint32_t)lb[3] << 16);
}

__device__ __forceinline__ float sigmoidf_(float x) {
    return 1.0f / (1.0f + __expf(-x));
}

// ---------------- input-projection GEMM (unchanged, known-good) -------------
__global__ __launch_bounds__(256) void gru_gemm_in(
    const float* __restrict__ Aopt, const float* __restrict__ W,
    const float* __restrict__ bias, int dirIdx)
{
    const float* A = Aopt ? Aopt : g_seq;
    float* C = g_gx[dirIdx];

    __shared__ __nv_bfloat16 Ah[128][40];
    __shared__ __nv_bfloat16 Al[128][40];
    __shared__ __nv_bfloat16 Bh[128][40];
    __shared__ __nv_bfloat16 Bl[128][40];

    const int tid  = threadIdx.x;
    const int lane = tid & 31;
    const int warp = tid >> 5;
    const int wm   = warp >> 1;
    const int wn   = warp & 1;
    const int m0   = blockIdx.y * 128;
    const int n0   = blockIdx.x * 128;

    float acc[2][8][4];
#pragma unroll
    for (int i = 0; i < 2; i++)
#pragma unroll
        for (int j = 0; j < 8; j++)
#pragma unroll
            for (int k = 0; k < 4; k++) acc[i][j][k] = 0.f;

    const int c4 = (tid & 7) * 4;
    const int r0 = tid >> 3;

    float4 ra[4], rb[4];
#pragma unroll
    for (int i = 0; i < 4; i++) {
        ra[i] = *reinterpret_cast<const float4*>(&A[(m0 + r0 + i * 32) * K_IN + c4]);
        rb[i] = *reinterpret_cast<const float4*>(&W[(n0 + r0 + i * 32) * K_IN + c4]);
    }

    for (int kt = 0; kt < K_IN; kt += 32) {
#pragma unroll
        for (int i = 0; i < 4; i++) {
            split4(ra[i], &Ah[r0 + i * 32][c4], &Al[r0 + i * 32][c4]);
            split4(rb[i], &Bh[r0 + i * 32][c4], &Bl[r0 + i * 32][c4]);
        }
        __syncthreads();
        if (kt + 32 < K_IN) {
#pragma unroll
            for (int i = 0; i < 4; i++) {
                ra[i] = *reinterpret_cast<const float4*>(&A[(m0 + r0 + i * 32) * K_IN + kt + 32 + c4]);
                rb[i] = *reinterpret_cast<const float4*>(&W[(n0 + r0 + i * 32) * K_IN + kt + 32 + c4]);
            }
        }
#pragma unroll
        for (int k16 = 0; k16 < 2; k16++) {
            const int kk   = k16 * 16 + (lane & 3) * 2;
            const int arow = wm * 32 + (lane >> 2);
            uint32_t ahf[2][4], alf[2][4];
#pragma unroll
            for (int mt = 0; mt < 2; mt++) {
                const int rr = arow + mt * 16;
                ahf[mt][0] = *reinterpret_cast<const uint32_t*>(&Ah[rr][kk]);
                ahf[mt][1] = *reinterpret_cast<const uint32_t*>(&Ah[rr + 8][kk]);
                ahf[mt][2] = *reinterpret_cast<const uint32_t*>(&Ah[rr][kk + 8]);
                ahf[mt][3] = *reinterpret_cast<const uint32_t*>(&Ah[rr + 8][kk + 8]);
                alf[mt][0] = *reinterpret_cast<const uint32_t*>(&Al[rr][kk]);
                alf[mt][1] = *reinterpret_cast<const uint32_t*>(&Al[rr + 8][kk]);
                alf[mt][2] = *reinterpret_cast<const uint32_t*>(&Al[rr][kk + 8]);
                alf[mt][3] = *reinterpret_cast<const uint32_t*>(&Al[rr + 8][kk + 8]);
            }
            uint32_t bhf[8][2], blf[8][2];
            const int brow = wn * 64 + (lane >> 2);
#pragma unroll
            for (int nt = 0; nt < 8; nt++) {
                const int rr = brow + nt * 8;
                bhf[nt][0] = *reinterpret_cast<const uint32_t*>(&Bh[rr][kk]);
                bhf[nt][1] = *reinterpret_cast<const uint32_t*>(&Bh[rr][kk + 8]);
                blf[nt][0] = *reinterpret_cast<const uint32_t*>(&Bl[rr][kk]);
                blf[nt][1] = *reinterpret_cast<const uint32_t*>(&Bl[rr][kk + 8]);
            }
#pragma unroll
            for (int mt = 0; mt < 2; mt++)
#pragma unroll
                for (int nt = 0; nt < 8; nt++) {
                    mma_bf16(acc[mt][nt], ahf[mt], bhf[nt]);
                    mma_bf16(acc[mt][nt], ahf[mt], blf[nt]);
                    mma_bf16(acc[mt][nt], alf[mt], bhf[nt]);
                }
        }
        __syncthreads();
    }

#pragma unroll
    for (int mt = 0; mt < 2; mt++)
#pragma unroll
        for (int nt = 0; nt < 8; nt++) {
            const int row = m0 + wm * 32 + mt * 16 + (lane >> 2);
            const int col = n0 + wn * 64 + nt * 8 + (lane & 3) * 2;
            const float b0 = bias[col], b1 = bias[col + 1];
            C[row * G3H + col]           = acc[mt][nt][0] + b0;
            C[row * G3H + col + 1]       = acc[mt][nt][1] + b1;
            C[(row + 8) * G3H + col]     = acc[mt][nt][2] + b0;
            C[(row + 8) * G3H + col + 1] = acc[mt][nt][3] + b1;
        }
}

// ---------------- persistent recurrent layer kernel -------------------------
// grid (64, 2), 128 threads/block, 1 block/SM (218.6KB dyn smem).
// Whh slab (48 gate rows x 1024) resident in SMEM as split bf16.
// h streamed per step from pre-split global buffers via cp.async + ldmatrix.
__global__ __launch_bounds__(128) void gru_layer(
    const float* __restrict__ whh_l, const float* __restrict__ bhh_l,
    const float* __restrict__ h0l, int layer, float* __restrict__ dout)
{
    extern __shared__ __nv_bfloat16 sm[];
    __nv_bfloat16* Bh = sm;                       // [48][BPAD]
    __nv_bfloat16* Bl = sm + 48 * BPAD;
    __nv_bfloat16* Ah = sm + 2 * 48 * BPAD;       // [2][64][APAD]
    __nv_bfloat16* Al = Ah + 2 * 64 * APAD;

    const int dir  = blockIdx.y;
    const int nc0  = blockIdx.x * 16;
    const int bid  = blockIdx.y * 64 + blockIdx.x;
    const int tid  = threadIdx.x;
    const int lane = tid & 31;
    const int warp = tid >> 5;

    const float* whh = whh_l + dir * G3H * H_SZ;
    const float* bhh = bhh_l + dir * G3H;
    const float* gx  = g_gx[dir];

    // --- prologue: Whh slab -> SMEM split (once per layer) ---
    for (int i = tid; i < 48 * 256; i += 128) {
        const int row = i >> 8;
        const int q   = (i & 255) * 4;
        const int grow = (row >> 4) * H_SZ + nc0 + (row & 15);
        float4 v = *reinterpret_cast<const float4*>(&whh[grow * H_SZ + q]);
        split4(v, &Bh[row * BPAD + q], &Bl[row * BPAD + q]);
    }
    // --- prologue: h0 -> split bf16 + exact fp32 (cooperative, all blocks) ---
    for (int i = bid * 128 + tid; i < 2 * B_SZ * H_SZ; i += NBLK * 128) {
        const int d = i >> 16;
        const int off = i & 65535;
        float v = h0l[i];
        __nv_bfloat16 hi = __float2bfloat16_rn(v);
        __nv_bfloat16 lo = __float2bfloat16_rn(v - __bfloat162float(hi));
        g_hs[d][0][0][off] = hi;
        g_hs[d][0][1][off] = lo;
        g_hf[0][d][off] = v;
    }
    grid_barrier();

    for (int s = 0; s < T_LEN; s++) {
        const int par = s & 1;
        const __nv_bfloat16* hh = g_hs[dir][par][0];
        const __nv_bfloat16* hl = g_hs[dir][par][1];

        float acc[6][4];
#pragma unroll
        for (int i = 0; i < 6; i++)
#pragma unroll
            for (int j = 0; j < 4; j++) acc[i][j] = 0.f;

        // issue chunk 0
        {
#pragma unroll
            for (int it = 0; it < 2; it++) {
                const int i = tid + it * 128;
                const int row = i >> 2, q = (i & 3) * 8;
                cp16(&Ah[row * APAD + q], &hh[row * H_SZ + q]);
                cp16(&Al[row * APAD + q], &hl[row * H_SZ + q]);
            }
            asm volatile("cp.async.commit_group;\n" ::: "memory");
        }

        int buf = 0;
        for (int kc = 0; kc < NCHUNK; kc++) {
            if (kc + 1 < NCHUNK) {
                const int nb = buf ^ 1;
#pragma unroll
                for (int it = 0; it < 2; it++) {
                    const int i = tid + it * 128;
                    const int row = i >> 2, q = (i & 3) * 8;
                    cp16(&Ah[nb * 64 * APAD + row * APAD + q],
                         &hh[row * H_SZ + (kc + 1) * CHUNK + q]);
                    cp16(&Al[nb * 64 * APAD + row * APAD + q],
                         &hl[row * H_SZ + (kc + 1) * CHUNK + q]);
                }
                asm volatile("cp.async.commit_group;\n" ::: "memory");
                asm volatile("cp.async.wait_group 1;\n" ::: "memory");
            } else {
                asm volatile("cp.async.wait_group 0;\n" ::: "memory");
            }
            __syncthreads();

#pragma unroll
            for (int k16 = 0; k16 < 2; k16++) {
                const int tl = lane >> 3, tr = lane & 7;
                uint32_t ahf[4], alf[4];
                {
                    const int ar = warp * 16 + (tl & 1) * 8 + tr;
                    const int ak = k16 * 16 + (tl >> 1) * 8;
                    ldsm_x4(ahf, &Ah[buf * 64 * APAD + ar * APAD + ak]);
                    ldsm_x4(alf, &Al[buf * 64 * APAD + ar * APAD + ak]);
                }
                uint32_t bh[12], bl[12];
                {
                    const int kb = kc * CHUNK + k16 * 16 + (tl & 1) * 8;
                    const int rg = (tl >> 1) * 8 + tr;
#pragma unroll
                    for (int p = 0; p < 3; p++) {
                        ldsm_x4(&bh[p * 4], &Bh[(p * 16 + rg) * BPAD + kb]);
                        ldsm_x4(&bl[p * 4], &Bl[(p * 16 + rg) * BPAD + kb]);
                    }
                }
#pragma unroll
                for (int nt = 0; nt < 6; nt++) {
                    const int base = (nt >> 1) * 4 + (nt & 1) * 2;
                    mma_bf16(acc[nt], ahf, bh[base], bh[base + 1]);
                    mma_bf16(acc[nt], ahf, bl[base], bl[base + 1]);
                    mma_bf16(acc[nt], alf, bh[base], bh[base + 1]);
                }
            }
            __syncthreads();
            buf ^= 1;
        }

        // --- fused GRU gate epilogue ---
        const float* hfprev = g_hf[par][dir];
        float* hfnext = g_hf[par ^ 1][dir];
        __nv_bfloat16* nhh = g_hs[dir][par ^ 1][0];
        __nv_bfloat16* nhl = g_hs[dir][par ^ 1][1];
        const int t = dir ? (T_LEN - 1 - s) : s;
        const int rbase = warp * 16 + (lane >> 2);
#pragma unroll
        for (int rs = 0; rs < 2; rs++) {
            const int b = rbase + rs * 8;
#pragma unroll
            for (int tp = 0; tp < 2; tp++) {
#pragma unroll
                for (int j = 0; j < 2; j++) {
                    const int reg = rs * 2 + j;
                    const int c = nc0 + tp * 8 + (lane & 3) * 2 + j;
                    float ghr = acc[tp][reg]     + bhh[c];
                    float ghz = acc[tp + 2][reg] + bhh[H_SZ + c];
                    float ghn = acc[tp + 4][reg] + bhh[2 * H_SZ + c];
                    const float* gxrow = &gx[(t * B_SZ + b) * G3H];
                    float rg = sigmoidf_(gxrow[c] + ghr);
                    float zg = sigmoidf_(gxrow[H_SZ + c] + ghz);
                    float ng = tanhf(gxrow[2 * H_SZ + c] + rg * ghn);
                    float hp = hfprev[b * H_SZ + c];
                    float hn = ng + zg * (hp - ng);
                    hfnext[b * H_SZ + c] = hn;
                    __nv_bfloat16 hi = __float2bfloat16_rn(hn);
                    __nv_bfloat16 lo = __float2bfloat16_rn(hn - __bfloat162float(hi));
                    nhh[b * H_SZ + c] = hi;
                    nhl[b * H_SZ + c] = lo;
                    g_seq[(t * B_SZ + b) * (2 * H_SZ) + dir * H_SZ + c] = hn;
                    if (s == T_LEN - 1)
                        dout[(layer * 2 + dir) * B_SZ * H_SZ + b * H_SZ + c] = hn;
                }
            }
        }
        grid_barrier();
    }
}

// ---------------- launch ----------------------------------------------------
extern "C" void kernel_launch(void* const* d_in, const int* in_sizes, int n_in,
                              void* d_out, int out_size) {
    const float* x   = (const float*)d_in[0];   // [T,B,2048]
    const float* h0  = (const float*)d_in[1];   // [6,B,H]
    const float* wih = (const float*)d_in[2];   // [3,2,3072,2048]
    const float* whh = (const float*)d_in[3];   // [3,2,3072,1024]
    const float* bih = (const float*)d_in[4];   // [3,2,3072]
    const float* bhh = (const float*)d_in[5];   // [3,2,3072]
    float* out = (float*)d_out;                 // [6,B,H]

    cudaFuncSetAttribute(gru_layer, cudaFuncAttributeMaxDynamicSharedMemorySize,
                         SMEM_BYTES);

    const dim3 ggrid(G3H / 128, MROWS / 128);   // (24, 128)
    const dim3 lgrid(H_SZ / 16, 2);             // (64, 2)

    for (int l = 0; l < 3; l++) {
        const float* Ain = (l == 0) ? x : nullptr;   // null => g_seq
        for (int d = 0; d < 2; d++) {
            gru_gemm_in<<<ggrid, 256>>>(Ain,
                                        wih + (l * 2 + d) * G3H * K_IN,
                                        bih + (l * 2 + d) * G3H, d);
        }
        gru_layer<<<lgrid, 128, SMEM_BYTES>>>(whh + l * 2 * G3H * H_SZ,
                                              bhh + l * 2 * G3H,
                                              h0 + l * 2 * B_SZ * H_SZ, l, out);
    }
}

// round 11
// speedup vs baseline: 1.3385x; 1.2167x over previous
#include <cuda_runtime.h>
#include <cuda_bf16.h>
#include <cstdint>

#define T_LEN 256
#define B_SZ  64
#define H_SZ  1024
#define K_IN  2048
#define G3H   3072
#define MROWS (T_LEN * B_SZ)   // 16384

#define BPAD   1032             // Whh smem row stride (bf16 elems)
#define APAD   24               // h-chunk smem row stride (bf16 elems)
#define NCHUNK 32               // 32 chunks x (16 K per half x 2 halves)
// SMEM: Whh hi+lo (2*48*1032*2B) + A stage (2 hilo * 2 buf * 2 half * 64 * 24 * 2B)
#define SMEM_BYTES (2 * 48 * BPAD * 2 + 2 * 2 * 2 * 64 * APAD * 2)  // 222720

// ---------------- scratch (device globals; no allocation allowed) ----------
static __device__ float g_gx[2][MROWS * G3H];        // per-dir input gates, fp32
static __device__ float g_seq[MROWS * 2 * H_SZ];     // layer output sequence [T,B,2H]
static __device__ __align__(16) __nv_bfloat16 g_hs[2][2][2][B_SZ * H_SZ]; // [dir][par][hi/lo]

// ---------------- per-direction grid barrier --------------------------------
static __device__ unsigned g_cnt2[2] = {0, 0};
static __device__ volatile unsigned g_gen2[2] = {0, 0};

__device__ __forceinline__ void dir_barrier(int dir) {
    __syncthreads();
    if (threadIdx.x == 0) {
        __threadfence();
        unsigned gen = g_gen2[dir];
        if (atomicAdd(&g_cnt2[dir], 1) == 63) {
            g_cnt2[dir] = 0;
            __threadfence();
            g_gen2[dir] = gen + 1;
        } else {
            while (g_gen2[dir] == gen) { __nanosleep(32); }
        }
        __threadfence();
    }
    __syncthreads();
}

// ---------------- helpers --------------------------------------------------
__device__ __forceinline__ void mma_bf16(float (&c)[4], const uint32_t (&a)[4],
                                         const uint32_t (&b)[2]) {
    asm volatile(
        "mma.sync.aligned.m16n8k16.row.col.f32.bf16.bf16.f32 "
        "{%0,%1,%2,%3}, {%4,%5,%6,%7}, {%8,%9}, {%0,%1,%2,%3};\n"
        : "+f"(c[0]), "+f"(c[1]), "+f"(c[2]), "+f"(c[3])
        : "r"(a[0]), "r"(a[1]), "r"(a[2]), "r"(a[3]), "r"(b[0]), "r"(b[1]));
}
__device__ __forceinline__ void mma_bf16(float (&c)[4], const uint32_t (&a)[4],
                                         uint32_t b0, uint32_t b1) {
    asm volatile(
        "mma.sync.aligned.m16n8k16.row.col.f32.bf16.bf16.f32 "
        "{%0,%1,%2,%3}, {%4,%5,%6,%7}, {%8,%9}, {%0,%1,%2,%3};\n"
        : "+f"(c[0]), "+f"(c[1]), "+f"(c[2]), "+f"(c[3])
        : "r"(a[0]), "r"(a[1]), "r"(a[2]), "r"(a[3]), "r"(b0), "r"(b1));
}

__device__ __forceinline__ void ldsm_x4(uint32_t* r, const void* p) {
    uint32_t a = (uint32_t)__cvta_generic_to_shared(p);
    asm volatile("ldmatrix.sync.aligned.m8n8.x4.shared.b16 {%0,%1,%2,%3}, [%4];\n"
                 : "=r"(r[0]), "=r"(r[1]), "=r"(r[2]), "=r"(r[3]) : "r"(a));
}

__device__ __forceinline__ void cp16(void* s, const void* g) {
    uint32_t sa = (uint32_t)__cvta_generic_to_shared(s);
    asm volatile("cp.async.cg.shared.global [%0], [%1], 16;\n" :: "r"(sa), "l"(g));
}

__device__ __forceinline__ void split4(const float4 v, __nv_bfloat16* hi, __nv_bfloat16* lo) {
    float f[4] = {v.x, v.y, v.z, v.w};
    unsigned short hb[4], lb[4];
#pragma unroll
    for (int i = 0; i < 4; i++) {
        __nv_bfloat16 h = __float2bfloat16_rn(f[i]);
        float r = f[i] - __bfloat162float(h);
        __nv_bfloat16 l = __float2bfloat16_rn(r);
        hb[i] = __bfloat16_as_ushort(h);
        lb[i] = __bfloat16_as_ushort(l);
    }
    *reinterpret_cast<uint32_t*>(hi)     = (uint32_t)hb[0] | ((uint32_t)hb[1] << 16);
    *reinterpret_cast<uint32_t*>(hi + 2) = (uint32_t)hb[2] | ((uint32_t)hb[3] << 16);
    *reinterpret_cast<uint32_t*>(lo)     = (uint32_t)lb[0] | ((uint32_t)lb[1] << 16);
    *reinterpret_cast<uint32_t*>(lo + 2) = (uint32_t)lb[2] | ((uint32_t)lb[3] << 16);
}

__device__ __forceinline__ float sigmoidf_(float x) {
    return 1.0f / (1.0f + __expf(-x));
}

// ---------------- input-projection GEMM ------------------------------------
// C = A @ W^T + bias (+ bias2 for cols < 2H: folds bhh of r,z gates)
__global__ __launch_bounds__(256) void gru_gemm_in(
    const float* __restrict__ Aopt, const float* __restrict__ W,
    const float* __restrict__ bias, const float* __restrict__ bias2, int dirIdx)
{
    const float* A = Aopt ? Aopt : g_seq;
    float* C = g_gx[dirIdx];

    __shared__ __nv_bfloat16 Ah[128][40];
    __shared__ __nv_bfloat16 Al[128][40];
    __shared__ __nv_bfloat16 Bh[128][40];
    __shared__ __nv_bfloat16 Bl[128][40];

    const int tid  = threadIdx.x;
    const int lane = tid & 31;
    const int warp = tid >> 5;
    const int wm   = warp >> 1;
    const int wn   = warp & 1;
    const int m0   = blockIdx.y * 128;
    const int n0   = blockIdx.x * 128;

    float acc[2][8][4];
#pragma unroll
    for (int i = 0; i < 2; i++)
#pragma unroll
        for (int j = 0; j < 8; j++)
#pragma unroll
            for (int k = 0; k < 4; k++) acc[i][j][k] = 0.f;

    const int c4 = (tid & 7) * 4;
    const int r0 = tid >> 3;

    float4 ra[4], rb[4];
#pragma unroll
    for (int i = 0; i < 4; i++) {
        ra[i] = *reinterpret_cast<const float4*>(&A[(m0 + r0 + i * 32) * K_IN + c4]);
        rb[i] = *reinterpret_cast<const float4*>(&W[(n0 + r0 + i * 32) * K_IN + c4]);
    }

    for (int kt = 0; kt < K_IN; kt += 32) {
#pragma unroll
        for (int i = 0; i < 4; i++) {
            split4(ra[i], &Ah[r0 + i * 32][c4], &Al[r0 + i * 32][c4]);
            split4(rb[i], &Bh[r0 + i * 32][c4], &Bl[r0 + i * 32][c4]);
        }
        __syncthreads();
        if (kt + 32 < K_IN) {
#pragma unroll
            for (int i = 0; i < 4; i++) {
                ra[i] = *reinterpret_cast<const float4*>(&A[(m0 + r0 + i * 32) * K_IN + kt + 32 + c4]);
                rb[i] = *reinterpret_cast<const float4*>(&W[(n0 + r0 + i * 32) * K_IN + kt + 32 + c4]);
            }
        }
#pragma unroll
        for (int k16 = 0; k16 < 2; k16++) {
            const int kk   = k16 * 16 + (lane & 3) * 2;
            const int arow = wm * 32 + (lane >> 2);
            uint32_t ahf[2][4], alf[2][4];
#pragma unroll
            for (int mt = 0; mt < 2; mt++) {
                const int rr = arow + mt * 16;
                ahf[mt][0] = *reinterpret_cast<const uint32_t*>(&Ah[rr][kk]);
                ahf[mt][1] = *reinterpret_cast<const uint32_t*>(&Ah[rr + 8][kk]);
                ahf[mt][2] = *reinterpret_cast<const uint32_t*>(&Ah[rr][kk + 8]);
                ahf[mt][3] = *reinterpret_cast<const uint32_t*>(&Ah[rr + 8][kk + 8]);
                alf[mt][0] = *reinterpret_cast<const uint32_t*>(&Al[rr][kk]);
                alf[mt][1] = *reinterpret_cast<const uint32_t*>(&Al[rr + 8][kk]);
                alf[mt][2] = *reinterpret_cast<const uint32_t*>(&Al[rr][kk + 8]);
                alf[mt][3] = *reinterpret_cast<const uint32_t*>(&Al[rr + 8][kk + 8]);
            }
            uint32_t bhf[8][2], blf[8][2];
            const int brow = wn * 64 + (lane >> 2);
#pragma unroll
            for (int nt = 0; nt < 8; nt++) {
                const int rr = brow + nt * 8;
                bhf[nt][0] = *reinterpret_cast<const uint32_t*>(&Bh[rr][kk]);
                bhf[nt][1] = *reinterpret_cast<const uint32_t*>(&Bh[rr][kk + 8]);
                blf[nt][0] = *reinterpret_cast<const uint32_t*>(&Bl[rr][kk]);
                blf[nt][1] = *reinterpret_cast<const uint32_t*>(&Bl[rr][kk + 8]);
            }
#pragma unroll
            for (int mt = 0; mt < 2; mt++)
#pragma unroll
                for (int nt = 0; nt < 8; nt++) {
                    mma_bf16(acc[mt][nt], ahf[mt], bhf[nt]);
                    mma_bf16(acc[mt][nt], ahf[mt], blf[nt]);
                    mma_bf16(acc[mt][nt], alf[mt], bhf[nt]);
                }
        }
        __syncthreads();
    }

#pragma unroll
    for (int mt = 0; mt < 2; mt++)
#pragma unroll
        for (int nt = 0; nt < 8; nt++) {
            const int row = m0 + wm * 32 + mt * 16 + (lane >> 2);
            const int col = n0 + wn * 64 + nt * 8 + (lane & 3) * 2;
            float b0 = bias[col], b1 = bias[col + 1];
            if (col < 2 * H_SZ) { b0 += bias2[col]; b1 += bias2[col + 1]; }
            C[row * G3H + col]           = acc[mt][nt][0] + b0;
            C[row * G3H + col + 1]       = acc[mt][nt][1] + b1;
            C[(row + 8) * G3H + col]     = acc[mt][nt][2] + b0;
            C[(row + 8) * G3H + col + 1] = acc[mt][nt][3] + b1;
        }
}

// ---------------- persistent recurrent layer kernel -------------------------
// grid (64, 2), 256 threads (8 warps). K-split: warps 0-3 K[0:512], 4-7 K[512:1024].
// Whh slab resident in SMEM (split bf16). gx prefetched to regs. h fp32 in regs.
__global__ __launch_bounds__(256) void gru_layer(
    const float* __restrict__ whh_l, const float* __restrict__ bhh_l,
    const float* __restrict__ h0l, int layer, float* __restrict__ dout)
{
    extern __shared__ __nv_bfloat16 sm[];
    __nv_bfloat16* Bh = sm;                        // [48][BPAD]
    __nv_bfloat16* Bl = sm + 48 * BPAD;
    __nv_bfloat16* Astage = sm + 2 * 48 * BPAD;    // hi: [buf][half][64][APAD], then lo
    __nv_bfloat16* Ahs = Astage;
    __nv_bfloat16* Als = Astage + 2 * 2 * 64 * APAD;

    const int dir  = blockIdx.y;
    const int nc0  = blockIdx.x * 16;
    const int tid  = threadIdx.x;
    const int lane = tid & 31;
    const int warp = tid >> 5;
    const int w4   = warp & 3;
    const int half = warp >> 2;

    const float* whh = whh_l + dir * G3H * H_SZ;
    const float* bhh = bhh_l + dir * G3H;
    const float* gx  = g_gx[dir];

    // --- prologue: Whh slab -> SMEM split ---
    for (int i = tid; i < 48 * 256; i += 256) {
        const int row = i >> 8;
        const int q   = (i & 255) * 4;
        const int grow = (row >> 4) * H_SZ + nc0 + (row & 15);
        float4 v = *reinterpret_cast<const float4*>(&whh[grow * H_SZ + q]);
        split4(v, &Bh[row * BPAD + q], &Bl[row * BPAD + q]);
    }
    // --- prologue: h0 -> split bf16 (this dir's blocks init this dir's buffer) ---
    for (int i = blockIdx.x * 256 + tid; i < B_SZ * H_SZ; i += 64 * 256) {
        float v = h0l[dir * B_SZ * H_SZ + i];
        __nv_bfloat16 hi = __float2bfloat16_rn(v);
        __nv_bfloat16 lo = __float2bfloat16_rn(v - __bfloat162float(hi));
        g_hs[dir][0][0][i] = hi;
        g_hs[dir][0][1][i] = lo;
    }

    // --- persistent per-thread epilogue state (warps 0-3 only) ---
    const int rbase = w4 * 16 + (lane >> 2);
    float hp[8], bn[4];
    if (warp < 4) {
#pragma unroll
        for (int rs = 0; rs < 2; rs++)
#pragma unroll
            for (int tp = 0; tp < 2; tp++)
#pragma unroll
                for (int j = 0; j < 2; j++) {
                    const int b = rbase + rs * 8;
                    const int c = nc0 + tp * 8 + (lane & 3) * 2 + j;
                    hp[rs * 4 + tp * 2 + j] = h0l[dir * B_SZ * H_SZ + b * H_SZ + c];
                }
#pragma unroll
        for (int tp = 0; tp < 2; tp++)
#pragma unroll
            for (int j = 0; j < 2; j++)
                bn[tp * 2 + j] = bhh[2 * H_SZ + nc0 + tp * 8 + (lane & 3) * 2 + j];
    }
    dir_barrier(dir);

    // per-thread cp.async mapping (same every chunk)
    const int cp_half = tid >> 7;
    const int cp_row  = (tid >> 1) & 63;
    const int cp_q    = (tid & 1) * 8;

    for (int s = 0; s < T_LEN; s++) {
        const int par = s & 1;
        const __nv_bfloat16* hh = g_hs[dir][par][0];
        const __nv_bfloat16* hl = g_hs[dir][par][1];
        const int t = dir ? (T_LEN - 1 - s) : s;

        // issue chunk 0
        {
            const int gcol = cp_half * 512 + cp_q;
            const int aoff = (cp_half * 64 + cp_row) * APAD + cp_q;
            cp16(&Ahs[aoff], &hh[cp_row * H_SZ + gcol]);
            cp16(&Als[aoff], &hl[cp_row * H_SZ + gcol]);
            asm volatile("cp.async.commit_group;\n" ::: "memory");
        }

        // prefetch gx into registers (latency hidden behind mma loop)
        float pr[8], pz[8], pn[8];
        if (warp < 4) {
#pragma unroll
            for (int rs = 0; rs < 2; rs++)
#pragma unroll
                for (int tp = 0; tp < 2; tp++)
#pragma unroll
                    for (int j = 0; j < 2; j++) {
                        const int o = rs * 4 + tp * 2 + j;
                        const int b = rbase + rs * 8;
                        const int c = nc0 + tp * 8 + (lane & 3) * 2 + j;
                        const float* g = gx + (t * B_SZ + b) * G3H;
                        pr[o] = __ldg(g + c);
                        pz[o] = __ldg(g + H_SZ + c);
                        pn[o] = __ldg(g + 2 * H_SZ + c);
                    }
        }

        float acc[6][4];
#pragma unroll
        for (int i = 0; i < 6; i++)
#pragma unroll
            for (int j = 0; j < 4; j++) acc[i][j] = 0.f;

        int buf = 0;
        for (int kc = 0; kc < NCHUNK; kc++) {
            if (kc + 1 < NCHUNK) {
                const int nb = buf ^ 1;
                const int gcol = cp_half * 512 + (kc + 1) * 16 + cp_q;
                const int aoff = ((nb * 2 + cp_half) * 64 + cp_row) * APAD + cp_q;
                cp16(&Ahs[aoff], &hh[cp_row * H_SZ + gcol]);
                cp16(&Als[aoff], &hl[cp_row * H_SZ + gcol]);
                asm volatile("cp.async.commit_group;\n" ::: "memory");
                asm volatile("cp.async.wait_group 1;\n" ::: "memory");
            } else {
                asm volatile("cp.async.wait_group 0;\n" ::: "memory");
            }
            __syncthreads();

            const int tl = lane >> 3, tr = lane & 7;
            uint32_t ahf[4], alf[4];
            {
                const int ar = w4 * 16 + (tl & 1) * 8 + tr;
                const int ak = (tl >> 1) * 8;
                const int aoff = ((buf * 2 + half) * 64 + ar) * APAD + ak;
                ldsm_x4(ahf, &Ahs[aoff]);
                ldsm_x4(alf, &Als[aoff]);
            }
            uint32_t bh[12], bl[12];
            {
                const int kb = half * 512 + kc * 16 + (tl & 1) * 8;
                const int rg = (tl >> 1) * 8 + tr;
#pragma unroll
                for (int p = 0; p < 3; p++) {
                    ldsm_x4(&bh[p * 4], &Bh[(p * 16 + rg) * BPAD + kb]);
                    ldsm_x4(&bl[p * 4], &Bl[(p * 16 + rg) * BPAD + kb]);
                }
            }
#pragma unroll
            for (int nt = 0; nt < 6; nt++) {
                const int base = (nt >> 1) * 4 + (nt & 1) * 2;
                mma_bf16(acc[nt], ahf, bh[base], bh[base + 1]);
                mma_bf16(acc[nt], ahf, bl[base], bl[base + 1]);
                mma_bf16(acc[nt], alf, bh[base], bh[base + 1]);
            }
            __syncthreads();
            buf ^= 1;
        }

        // --- K-split reduction via SMEM (reuse A staging area) ---
        float* red = reinterpret_cast<float*>(Astage);
        if (warp >= 4) {
#pragma unroll
            for (int nt = 0; nt < 6; nt++)
#pragma unroll
                for (int j = 0; j < 4; j++)
                    red[((w4 * 6 + nt) * 32 + lane) * 4 + j] = acc[nt][j];
        }
        __syncthreads();

        if (warp < 4) {
#pragma unroll
            for (int nt = 0; nt < 6; nt++)
#pragma unroll
                for (int j = 0; j < 4; j++)
                    acc[nt][j] += red[((w4 * 6 + nt) * 32 + lane) * 4 + j];

            __nv_bfloat16* nhh = g_hs[dir][par ^ 1][0];
            __nv_bfloat16* nhl = g_hs[dir][par ^ 1][1];
#pragma unroll
            for (int rs = 0; rs < 2; rs++) {
                const int b = rbase + rs * 8;
#pragma unroll
                for (int tp = 0; tp < 2; tp++) {
#pragma unroll
                    for (int j = 0; j < 2; j++) {
                        const int reg = rs * 2 + j;
                        const int o = rs * 4 + tp * 2 + j;
                        const int c = nc0 + tp * 8 + (lane & 3) * 2 + j;
                        float ghr = acc[tp][reg];
                        float ghz = acc[tp + 2][reg];
                        float ghn = acc[tp + 4][reg] + bn[tp * 2 + j];
                        float rg = sigmoidf_(pr[o] + ghr);
                        float zg = sigmoidf_(pz[o] + ghz);
                        float ng = tanhf(pn[o] + rg * ghn);
                        float hn = ng + zg * (hp[o] - ng);
                        hp[o] = hn;
                        __nv_bfloat16 hi = __float2bfloat16_rn(hn);
                        __nv_bfloat16 lo = __float2bfloat16_rn(hn - __bfloat162float(hi));
                        nhh[b * H_SZ + c] = hi;
                        nhl[b * H_SZ + c] = lo;
                        g_seq[(t * B_SZ + b) * (2 * H_SZ) + dir * H_SZ + c] = hn;
                        if (s == T_LEN - 1)
                            dout[(layer * 2 + dir) * B_SZ * H_SZ + b * H_SZ + c] = hn;
                    }
                }
            }
        }
        dir_barrier(dir);
    }
}

// ---------------- launch ----------------------------------------------------
extern "C" void kernel_launch(void* const* d_in, const int* in_sizes, int n_in,
                              void* d_out, int out_size) {
    const float* x   = (const float*)d_in[0];   // [T,B,2048]
    const float* h0  = (const float*)d_in[1];   // [6,B,H]
    const float* wih = (const float*)d_in[2];   // [3,2,3072,2048]
    const float* whh = (const float*)d_in[3];   // [3,2,3072,1024]
    const float* bih = (const float*)d_in[4];   // [3,2,3072]
    const float* bhh = (const float*)d_in[5];   // [3,2,3072]
    float* out = (float*)d_out;                 // [6,B,H]

    cudaFuncSetAttribute(gru_layer, cudaFuncAttributeMaxDynamicSharedMemorySize,
                         SMEM_BYTES);

    const dim3 ggrid(G3H / 128, MROWS / 128);   // (24, 128)
    const dim3 lgrid(H_SZ / 16, 2);             // (64, 2)

    for (int l = 0; l < 3; l++) {
        const float* Ain = (l == 0) ? x : nullptr;   // null => g_seq
        for (int d = 0; d < 2; d++) {
            gru_gemm_in<<<ggrid, 256>>>(Ain,
                                        wih + (l * 2 + d) * G3H * K_IN,
                                        bih + (l * 2 + d) * G3H,
                                        bhh + (l * 2 + d) * G3H, d);
        }
        gru_layer<<<lgrid, 256, SMEM_BYTES>>>(whh + l * 2 * G3H * H_SZ,
                                              bhh + l * 2 * G3H,
                                              h0 + l * 2 * B_SZ * H_SZ, l, out);
    }
}

// round 15
// speedup vs baseline: 1.5711x; 1.1738x over previous
#include <cuda_runtime.h>
#include <cuda_bf16.h>
#include <cstdint>

#define T_LEN 256
#define B_SZ  64
#define H_SZ  1024
#define K_IN  2048
#define G3H   3072
#define MROWS (T_LEN * B_SZ)   // 16384

#define BPAD   1032             // Whh smem row stride (bf16 elems)
#define NCHUNK 32               // 32 chunks x 16 K per half
// per-warp A stage: 2 bufs x (hi+lo) x 16 rows x 24 elems = 1536 bf16 = 3072B
#define AW_ELEMS 1536
#define SMEM_BYTES (2 * 48 * BPAD * 2 + 8 * AW_ELEMS * 2)   // 198144 + 24576 = 222720

// ---------------- scratch (device globals; no allocation allowed) ----------
static __device__ float g_gx[2][MROWS * G3H];        // per-dir input gates, fp32
static __device__ float g_seq[MROWS * 2 * H_SZ];     // layer output sequence [T,B,2H]
static __device__ __align__(16) __nv_bfloat16 g_hs[2][2][2][B_SZ * H_SZ]; // [dir][par][hi/lo]

// ---------------- per-direction grid barrier --------------------------------
static __device__ unsigned g_cnt2[2] = {0, 0};
static __device__ volatile unsigned g_gen2[2] = {0, 0};

__device__ __forceinline__ void dir_barrier(int dir) {
    __threadfence();          // make this thread's h stores visible chip-wide
    __syncthreads();
    if (threadIdx.x == 0) {
        unsigned gen = g_gen2[dir];
        if (atomicAdd(&g_cnt2[dir], 1) == 63) {
            g_cnt2[dir] = 0;
            __threadfence();
            g_gen2[dir] = gen + 1;
        } else {
            while (g_gen2[dir] == gen) { __nanosleep(32); }
        }
        __threadfence();
    }
    __syncthreads();
}

// ---------------- helpers --------------------------------------------------
__device__ __forceinline__ void mma_bf16(float (&c)[4], const uint32_t (&a)[4],
                                         const uint32_t (&b)[2]) {
    asm volatile(
        "mma.sync.aligned.m16n8k16.row.col.f32.bf16.bf16.f32 "
        "{%0,%1,%2,%3}, {%4,%5,%6,%7}, {%8,%9}, {%0,%1,%2,%3};\n"
        : "+f"(c[0]), "+f"(c[1]), "+f"(c[2]), "+f"(c[3])
        : "r"(a[0]), "r"(a[1]), "r"(a[2]), "r"(a[3]), "r"(b[0]), "r"(b[1]));
}
__device__ __forceinline__ void mma_bf16(float (&c)[4], const uint32_t (&a)[4],
                                         uint32_t b0, uint32_t b1) {
    asm volatile(
        "mma.sync.aligned.m16n8k16.row.col.f32.bf16.bf16.f32 "
        "{%0,%1,%2,%3}, {%4,%5,%6,%7}, {%8,%9}, {%0,%1,%2,%3};\n"
        : "+f"(c[0]), "+f"(c[1]), "+f"(c[2]), "+f"(c[3])
        : "r"(a[0]), "r"(a[1]), "r"(a[2]), "r"(a[3]), "r"(b0), "r"(b1));
}

__device__ __forceinline__ void ldsm_x4(uint32_t* r, const void* p) {
    uint32_t a = (uint32_t)__cvta_generic_to_shared(p);
    asm volatile("ldmatrix.sync.aligned.m8n8.x4.shared.b16 {%0,%1,%2,%3}, [%4];\n"
                 : "=r"(r[0]), "=r"(r[1]), "=r"(r[2]), "=r"(r[3]) : "r"(a));
}

__device__ __forceinline__ void cp16(void* s, const void* g) {
    uint32_t sa = (uint32_t)__cvta_generic_to_shared(s);
    asm volatile("cp.async.cg.shared.global [%0], [%1], 16;\n" :: "r"(sa), "l"(g));
}

__device__ __forceinline__ void split4(const float4 v, __nv_bfloat16* hi, __nv_bfloat16* lo) {
    float f[4] = {v.x, v.y, v.z, v.w};
    unsigned short hb[4], lb[4];
#pragma unroll
    for (int i = 0; i < 4; i++) {
        __nv_bfloat16 h = __float2bfloat16_rn(f[i]);
        float r = f[i] - __bfloat162float(h);
        __nv_bfloat16 l = __float2bfloat16_rn(r);
        hb[i] = __bfloat16_as_ushort(h);
        lb[i] = __bfloat16_as_ushort(l);
    }
    *reinterpret_cast<uint32_t*>(hi)     = (uint32_t)hb[0] | ((uint32_t)hb[1] << 16);
    *reinterpret_cast<uint32_t*>(hi + 2) = (uint32_t)hb[2] | ((uint32_t)hb[3] << 16);
    *reinterpret_cast<uint32_t*>(lo)     = (uint32_t)lb[0] | ((uint32_t)lb[1] << 16);
    *reinterpret_cast<uint32_t*>(lo + 2) = (uint32_t)lb[2] | ((uint32_t)lb[3] << 16);
}

__device__ __forceinline__ float sigmoidf_(float x) {
    return __fdividef(1.0f, 1.0f + __expf(-x));
}
__device__ __forceinline__ float tanhf_(float x) {
    float e = __expf(-2.0f * fabsf(x));
    float t = __fdividef(1.0f - e, 1.0f + e);
    return copysignf(t, x);
}

// ---------------- input-projection GEMM (known-good, unchanged) -------------
__global__ __launch_bounds__(256) void gru_gemm_in(
    const float* __restrict__ Aopt, const float* __restrict__ W,
    const float* __restrict__ bias, const float* __restrict__ bias2, int dirIdx)
{
    const float* A = Aopt ? Aopt : g_seq;
    float* C = g_gx[dirIdx];

    __shared__ __nv_bfloat16 Ah[128][40];
    __shared__ __nv_bfloat16 Al[128][40];
    __shared__ __nv_bfloat16 Bh[128][40];
    __shared__ __nv_bfloat16 Bl[128][40];

    const int tid  = threadIdx.x;
    const int lane = tid & 31;
    const int warp = tid >> 5;
    const int wm   = warp >> 1;
    const int wn   = warp & 1;
    const int m0   = blockIdx.y * 128;
    const int n0   = blockIdx.x * 128;

    float acc[2][8][4];
#pragma unroll
    for (int i = 0; i < 2; i++)
#pragma unroll
        for (int j = 0; j < 8; j++)
#pragma unroll
            for (int k = 0; k < 4; k++) acc[i][j][k] = 0.f;

    const int c4 = (tid & 7) * 4;
    const int r0 = tid >> 3;

    float4 ra[4], rb[4];
#pragma unroll
    for (int i = 0; i < 4; i++) {
        ra[i] = *reinterpret_cast<const float4*>(&A[(m0 + r0 + i * 32) * K_IN + c4]);
        rb[i] = *reinterpret_cast<const float4*>(&W[(n0 + r0 + i * 32) * K_IN + c4]);
    }

    for (int kt = 0; kt < K_IN; kt += 32) {
#pragma unroll
        for (int i = 0; i < 4; i++) {
            split4(ra[i], &Ah[r0 + i * 32][c4], &Al[r0 + i * 32][c4]);
            split4(rb[i], &Bh[r0 + i * 32][c4], &Bl[r0 + i * 32][c4]);
        }
        __syncthreads();
        if (kt + 32 < K_IN) {
#pragma unroll
            for (int i = 0; i < 4; i++) {
                ra[i] = *reinterpret_cast<const float4*>(&A[(m0 + r0 + i * 32) * K_IN + kt + 32 + c4]);
                rb[i] = *reinterpret_cast<const float4*>(&W[(n0 + r0 + i * 32) * K_IN + kt + 32 + c4]);
            }
        }
#pragma unroll
        for (int k16 = 0; k16 < 2; k16++) {
            const int kk   = k16 * 16 + (lane & 3) * 2;
            const int arow = wm * 32 + (lane >> 2);
            uint32_t ahf[2][4], alf[2][4];
#pragma unroll
            for (int mt = 0; mt < 2; mt++) {
                const int rr = arow + mt * 16;
                ahf[mt][0] = *reinterpret_cast<const uint32_t*>(&Ah[rr][kk]);
                ahf[mt][1] = *reinterpret_cast<const uint32_t*>(&Ah[rr + 8][kk]);
                ahf[mt][2] = *reinterpret_cast<const uint32_t*>(&Ah[rr][kk + 8]);
                ahf[mt][3] = *reinterpret_cast<const uint32_t*>(&Ah[rr + 8][kk + 8]);
                alf[mt][0] = *reinterpret_cast<const uint32_t*>(&Al[rr][kk]);
                alf[mt][1] = *reinterpret_cast<const uint32_t*>(&Al[rr + 8][kk]);
                alf[mt][2] = *reinterpret_cast<const uint32_t*>(&Al[rr][kk + 8]);
                alf[mt][3] = *reinterpret_cast<const uint32_t*>(&Al[rr + 8][kk + 8]);
            }
            uint32_t bhf[8][2], blf[8][2];
            const int brow = wn * 64 + (lane >> 2);
#pragma unroll
            for (int nt = 0; nt < 8; nt++) {
                const int rr = brow + nt * 8;
                bhf[nt][0] = *reinterpret_cast<const uint32_t*>(&Bh[rr][kk]);
                bhf[nt][1] = *reinterpret_cast<const uint32_t*>(&Bh[rr][kk + 8]);
                blf[nt][0] = *reinterpret_cast<const uint32_t*>(&Bl[rr][kk]);
                blf[nt][1] = *reinterpret_cast<const uint32_t*>(&Bl[rr][kk + 8]);
            }
#pragma unroll
            for (int mt = 0; mt < 2; mt++)
#pragma unroll
                for (int nt = 0; nt < 8; nt++) {
                    mma_bf16(acc[mt][nt], ahf[mt], bhf[nt]);
                    mma_bf16(acc[mt][nt], ahf[mt], blf[nt]);
                    mma_bf16(acc[mt][nt], alf[mt], bhf[nt]);
                }
        }
        __syncthreads();
    }

#pragma unroll
    for (int mt = 0; mt < 2; mt++)
#pragma unroll
        for (int nt = 0; nt < 8; nt++) {
            const int row = m0 + wm * 32 + mt * 16 + (lane >> 2);
            const int col = n0 + wn * 64 + nt * 8 + (lane & 3) * 2;
            float b0 = bias[col], b1 = bias[col + 1];
            if (col < 2 * H_SZ) { b0 += bias2[col]; b1 += bias2[col + 1]; }
            C[row * G3H + col]           = acc[mt][nt][0] + b0;
            C[row * G3H + col + 1]       = acc[mt][nt][1] + b1;
            C[(row + 8) * G3H + col]     = acc[mt][nt][2] + b0;
            C[(row + 8) * G3H + col + 1] = acc[mt][nt][3] + b1;
        }
}

// ---------------- persistent recurrent layer kernel -------------------------
// grid (64, 2), 256 threads (8 warps = 4 m-tiles x 2 K-halves).
// Whh (48 gate rows x 1024, split bf16) resident in SMEM.
// A (h) staging is WARP-PRIVATE: each warp cp.asyncs its own 16x16 chunk and
// waits on its own cp group -> ZERO __syncthreads in the 32-chunk MMA loop.
__global__ __launch_bounds__(256) void gru_layer(
    const float* __restrict__ whh_l, const float* __restrict__ bhh_l,
    const float* __restrict__ h0l, int layer, float* __restrict__ dout)
{
    extern __shared__ __nv_bfloat16 sm[];
    __nv_bfloat16* Bh = sm;                        // [48][BPAD]
    __nv_bfloat16* Bl = sm + 48 * BPAD;
    __nv_bfloat16* Astage = sm + 2 * 48 * BPAD;    // 8 x AW_ELEMS (warp-private)

    const int dir  = blockIdx.y;
    const int nc0  = blockIdx.x * 16;
    const int tid  = threadIdx.x;
    const int lane = tid & 31;
    const int warp = tid >> 5;
    const int w4   = warp & 3;     // m-tile
    const int kh   = warp >> 2;    // K half: 0 -> K[0:512), 1 -> K[512:1024)

    __nv_bfloat16* Aw = Astage + warp * AW_ELEMS;  // [buf][hi/lo][16][24]

    const float* whh = whh_l + dir * G3H * H_SZ;
    const float* bhh = bhh_l + dir * G3H;
    const float* gx  = g_gx[dir];
    const int writeSeq = (layer < 2);

    // --- prologue: Whh slab -> SMEM split ---
    for (int i = tid; i < 48 * 256; i += 256) {
        const int row = i >> 8;
        const int q   = (i & 255) * 4;
        const int grow = (row >> 4) * H_SZ + nc0 + (row & 15);
        float4 v = *reinterpret_cast<const float4*>(&whh[grow * H_SZ + q]);
        split4(v, &Bh[row * BPAD + q], &Bl[row * BPAD + q]);
    }
    // --- prologue: h0 -> split bf16 ---
    for (int i = blockIdx.x * 256 + tid; i < B_SZ * H_SZ; i += 64 * 256) {
        float v = h0l[dir * B_SZ * H_SZ + i];
        __nv_bfloat16 hi = __float2bfloat16_rn(v);
        __nv_bfloat16 lo = __float2bfloat16_rn(v - __bfloat162float(hi));
        g_hs[dir][0][0][i] = hi;
        g_hs[dir][0][1][i] = lo;
    }

    // --- persistent per-thread epilogue state: 4 outputs/thread ---
    const int ob = w4 * 16 + (lane >> 2) + kh * 8;   // batch row
    const int oc = nc0 + (lane & 3) * 2;             // col base (tp adds 8)
    float hp[4], bn[4];
#pragma unroll
    for (int tp = 0; tp < 2; tp++)
#pragma unroll
        for (int j = 0; j < 2; j++) {
            hp[tp * 2 + j] = h0l[dir * B_SZ * H_SZ + ob * H_SZ + oc + tp * 8 + j];
            bn[tp * 2 + j] = bhh[2 * H_SZ + oc + tp * 8 + j];
        }
    dir_barrier(dir);

    // warp-private cp mapping: lane -> (row, 8-elem segment)
    const int srow = lane >> 1;
    const int sseg = (lane & 1) * 8;
    // A ldsm mapping
    const int aoff = (lane & 15) * 24 + (lane >> 4) * 8;
    // B ldsm mapping
    const int tl = lane >> 3, tr = lane & 7;
    const int brg = (tl >> 1) * 8 + tr;
    const int bk8 = (tl & 1) * 8;

    for (int s = 0; s < T_LEN; s++) {
        const int par = s & 1;
        const __nv_bfloat16* hh = g_hs[dir][par][0];
        const __nv_bfloat16* hl = g_hs[dir][par][1];
        const int t = dir ? (T_LEN - 1 - s) : s;
        const long hrow = (long)(w4 * 16 + srow) * H_SZ + kh * 512 + sseg;

        // pre-issue chunks 0 and 1 (warp-private groups)
#pragma unroll
        for (int kc = 0; kc < 2; kc++) {
            __nv_bfloat16* d = Aw + kc * 768 + srow * 24 + sseg;
            cp16(d,       &hh[hrow + kc * 16]);
            cp16(d + 384, &hl[hrow + kc * 16]);
            asm volatile("cp.async.commit_group;\n" ::: "memory");
        }

        // prefetch gx (float2 x 6) -- consumed after the mma loop
        const float* gxrow = gx + ((long)t * B_SZ + ob) * G3H + oc;
        float2 pr[2], pz[2], pn[2];
#pragma unroll
        for (int tp = 0; tp < 2; tp++) {
            pr[tp] = __ldg((const float2*)(gxrow + tp * 8));
            pz[tp] = __ldg((const float2*)(gxrow + H_SZ + tp * 8));
            pn[tp] = __ldg((const float2*)(gxrow + 2 * H_SZ + tp * 8));
        }

        float acc[6][4];
#pragma unroll
        for (int i = 0; i < 6; i++)
#pragma unroll
            for (int j = 0; j < 4; j++) acc[i][j] = 0.f;

        for (int kc = 0; kc < NCHUNK; kc++) {
            const int buf = kc & 1;
            // B fragments (static smem, no dependency on cp)
            uint32_t bh[12], bl[12];
            const int kb = kh * 512 + kc * 16 + bk8;
#pragma unroll
            for (int p = 0; p < 3; p++) {
                ldsm_x4(&bh[p * 4], &Bh[(p * 16 + brg) * BPAD + kb]);
                ldsm_x4(&bl[p * 4], &Bl[(p * 16 + brg) * BPAD + kb]);
            }
            // wait for this warp's chunk kc
            if (kc < NCHUNK - 1) {
                asm volatile("cp.async.wait_group 1;\n" ::: "memory");
            } else {
                asm volatile("cp.async.wait_group 0;\n" ::: "memory");
            }
            uint32_t ahf[4], alf[4];
            ldsm_x4(ahf, Aw + buf * 768 + aoff);
            ldsm_x4(alf, Aw + buf * 768 + 384 + aoff);
#pragma unroll
            for (int nt = 0; nt < 6; nt++) {
                const int base = (nt >> 1) * 4 + (nt & 1) * 2;
                mma_bf16(acc[nt], ahf, bh[base], bh[base + 1]);
                mma_bf16(acc[nt], ahf, bl[base], bl[base + 1]);
                mma_bf16(acc[nt], alf, bh[base], bh[base + 1]);
            }
            // issue chunk kc+2 into the buffer just consumed
            if (kc + 2 < NCHUNK) {
                __nv_bfloat16* d = Aw + buf * 768 + srow * 24 + sseg;
                cp16(d,       &hh[hrow + (kc + 2) * 16]);
                cp16(d + 384, &hl[hrow + (kc + 2) * 16]);
                asm volatile("cp.async.commit_group;\n" ::: "memory");
            }
        }

        // --- K-split reduction via SMEM (reuse A staging area) ---
        float4* red = reinterpret_cast<float4*>(Astage);
        {
            const int rb = (kh * 4 + w4) * 6 * 32 + lane;
#pragma unroll
            for (int nt = 0; nt < 6; nt++)
                red[rb + nt * 32] = make_float4(acc[nt][0], acc[nt][1],
                                                acc[nt][2], acc[nt][3]);
        }
        __syncthreads();

        float g0[6], g1[6];
        {
            const int b0 = w4 * 6 * 32 + lane;
            const int b1 = (4 + w4) * 6 * 32 + lane;
#pragma unroll
            for (int nt = 0; nt < 6; nt++) {
                float4 r0 = red[b0 + nt * 32];
                float4 r1 = red[b1 + nt * 32];
                float sx = r0.x + r1.x, sy = r0.y + r1.y;
                float sz = r0.z + r1.z, sw = r0.w + r1.w;
                g0[nt] = kh ? sz : sx;     // reg half*2
                g1[nt] = kh ? sw : sy;     // reg half*2+1
            }
        }

        // --- fused GRU gate epilogue (all 8 warps, 4 outputs each thread) ---
        __nv_bfloat16* nhh = g_hs[dir][par ^ 1][0];
        __nv_bfloat16* nhl = g_hs[dir][par ^ 1][1];
#pragma unroll
        for (int tp = 0; tp < 2; tp++) {
            float rg0 = sigmoidf_(pr[tp].x + g0[tp]);
            float rg1 = sigmoidf_(pr[tp].y + g1[tp]);
            float zg0 = sigmoidf_(pz[tp].x + g0[tp + 2]);
            float zg1 = sigmoidf_(pz[tp].y + g1[tp + 2]);
            float ng0 = tanhf_(pn[tp].x + rg0 * (g0[tp + 4] + bn[tp * 2]));
            float ng1 = tanhf_(pn[tp].y + rg1 * (g1[tp + 4] + bn[tp * 2 + 1]));
            float hn0 = ng0 + zg0 * (hp[tp * 2]     - ng0);
            float hn1 = ng1 + zg1 * (hp[tp * 2 + 1] - ng1);
            hp[tp * 2]     = hn0;
            hp[tp * 2 + 1] = hn1;
            const int c = oc + tp * 8;
            __nv_bfloat16 h0b = __float2bfloat16_rn(hn0);
            __nv_bfloat16 h1b = __float2bfloat16_rn(hn1);
            __nv_bfloat162 hi2; hi2.x = h0b; hi2.y = h1b;
            __nv_bfloat162 lo2;
            lo2.x = __float2bfloat16_rn(hn0 - __bfloat162float(h0b));
            lo2.y = __float2bfloat16_rn(hn1 - __bfloat162float(h1b));
            *reinterpret_cast<__nv_bfloat162*>(&nhh[ob * H_SZ + c]) = hi2;
            *reinterpret_cast<__nv_bfloat162*>(&nhl[ob * H_SZ + c]) = lo2;
            if (writeSeq) {
                float2 sq; sq.x = hn0; sq.y = hn1;
                *reinterpret_cast<float2*>(
                    &g_seq[((long)t * B_SZ + ob) * (2 * H_SZ) + dir * H_SZ + c]) = sq;
            }
            if (s == T_LEN - 1) {
                float2 od; od.x = hn0; od.y = hn1;
                *reinterpret_cast<float2*>(
                    &dout[(layer * 2 + dir) * B_SZ * H_SZ + ob * H_SZ + c]) = od;
            }
        }
        dir_barrier(dir);
    }
}

// ---------------- launch ----------------------------------------------------
extern "C" void kernel_launch(void* const* d_in, const int* in_sizes, int n_in,
                              void* d_out, int out_size) {
    const float* x   = (const float*)d_in[0];   // [T,B,2048]
    const float* h0  = (const float*)d_in[1];   // [6,B,H]
    const float* wih = (const float*)d_in[2];   // [3,2,3072,2048]
    const float* whh = (const float*)d_in[3];   // [3,2,3072,1024]
    const float* bih = (const float*)d_in[4];   // [3,2,3072]
    const float* bhh = (const float*)d_in[5];   // [3,2,3072]
    float* out = (float*)d_out;                 // [6,B,H]

    cudaFuncSetAttribute(gru_layer, cudaFuncAttributeMaxDynamicSharedMemorySize,
                         SMEM_BYTES);

    const dim3 ggrid(G3H / 128, MROWS / 128);   // (24, 128)
    const dim3 lgrid(H_SZ / 16, 2);             // (64, 2)

    for (int l = 0; l < 3; l++) {
        const float* Ain = (l == 0) ? x : nullptr;   // null => g_seq
        for (int d = 0; d < 2; d++) {
            gru_gemm_in<<<ggrid, 256>>>(Ain,
                                        wih + (l * 2 + d) * G3H * K_IN,
                                        bih + (l * 2 + d) * G3H,
                                        bhh + (l * 2 + d) * G3H, d);
        }
        gru_layer<<<lgrid, 256, SMEM_BYTES>>>(whh + l * 2 * G3H * H_SZ,
                                              bhh + l * 2 * G3H,
                                              h0 + l * 2 * B_SZ * H_SZ, l, out);
    }
}